// round 13
// baseline (speedup 1.0000x reference)
#include <cuda_runtime.h>

// OnnxNonMaxSuppression: B=8, C=80, N=16384, max_out=50. Output float32.
//
// Round-13: phase-split pipeline (R12 post-mortem: monolithic CTA/lane
// couples a bandwidth phase to a latency phase; per-block critical paths
// serialized ~32K cyc). Three kernels:
//   0. zero:   reset per-lane candidate counters.
//   1. gather: 640x4 blocks stream scores (pure float4 + compare), append
//              top-chunk keys (score >= top-25-bucket threshold, E~200,
//              CAP=256) to per-lane global buffers.
//   2. walk:   640 blocks: sort keys (desc score, asc idx), prefetch boxes,
//              warp-0 ballot walk == exact greedy NMS; histogram fallback
//              (overflow or <50 picks) keeps it provably exact.

#define NMS_B      8
#define NMS_C      80
#define NMS_N      16384
#define NMS_LANES  (NMS_B * NMS_C)
#define NMS_MAXOUT 50
#define NT         256
#define SPLIT      4                 // gather blocks per lane
#define NBUCKET    1024
#define CAP        256
#define TARGET     128
#define IOU_THR    0.5f
#define SCORE_THR  0.5f
#define BITS_BASE  0x3F000001u       // smallest float bits > 0.5f
#define T0_BUCKET  999
#define T0_BITS    (BITS_BASE + ((unsigned)T0_BUCKET << 13))

__device__ unsigned long long g_keys[NMS_LANES * CAP];
__device__ int                g_cnt[NMS_LANES];

__device__ __forceinline__ unsigned score_bucket(unsigned bits) {
    unsigned bkt = (bits - BITS_BASE) >> 13;
    return bkt > (NBUCKET - 1) ? (NBUCKET - 1) : bkt;
}

// Reference-exact IoU rejection test (no-FMA, operand order preserved).
__device__ __forceinline__ bool iou_reject(
    float px1, float py1, float px2, float py2, float pa,
    float qx1, float qy1, float qx2, float qy2, float qa)
{
    float x1 = fmaxf(px1, qx1);
    float y1 = fmaxf(py1, qy1);
    float x2 = fminf(px2, qx2);
    float y2 = fminf(py2, qy2);
    float w  = fmaxf(x2 - x1, 0.0f);
    float h  = fmaxf(y2 - y1, 0.0f);
    float inter = __fmul_rn(w, h);
    float uni   = __fsub_rn(__fadd_rn(pa, qa), inter);
    float iou   = inter / fmaxf(uni, 1e-9f);
    return iou > IOU_THR;
}

__device__ __forceinline__ void sort256(unsigned long long* keys, int tid)
{
    #pragma unroll
    for (int k2 = 2; k2 <= CAP; k2 <<= 1) {
        for (int j = k2 >> 1; j > 0; j >>= 1) {
            int p = tid ^ j;
            if (p > tid) {
                unsigned long long a = keys[tid];
                unsigned long long bb = keys[p];
                bool up = ((tid & k2) == 0);
                if (up ? (a < bb) : (a > bb)) { keys[tid] = bb; keys[p] = a; }
            }
            __syncthreads();
        }
    }
}

// ---- kernel 0: reset counters ----
__global__ void zero_kernel() {
    int i = blockIdx.x * blockDim.x + threadIdx.x;
    if (i < NMS_LANES) g_cnt[i] = 0;
}

// ---- kernel 1: gather top-chunk candidates ----
__global__ void __launch_bounds__(NT) gather_kernel(
    const float* __restrict__ scores)   // [B, C, N]
{
    const int lane = blockIdx.x;
    const int part = blockIdx.y;
    const int tid  = threadIdx.x;

    const float4* sc4 = reinterpret_cast<const float4*>(
        scores + (size_t)lane * NMS_N);
    const int F4_PER_PART = NMS_N / 4 / SPLIT;      // 1024 float4
    const int base4 = part * F4_PER_PART;

    const float t0f = __uint_as_float(T0_BITS);
    #pragma unroll
    for (int k = 0; k < F4_PER_PART / NT; k++) {    // 4 float4 per thread
        int    i4 = base4 + k * NT + tid;
        float4 v4 = sc4[i4];
        float vs[4] = {v4.x, v4.y, v4.z, v4.w};
        #pragma unroll
        for (int q = 0; q < 4; q++) {
            if (vs[q] >= t0f) {                     // == bits >= T0_BITS
                int pos = atomicAdd(&g_cnt[lane], 1);
                if (pos < CAP) {
                    unsigned bits = __float_as_uint(vs[q]);
                    g_keys[lane * CAP + pos] =
                        ((unsigned long long)bits << 32)
                        | (unsigned)(~(unsigned)(i4 * 4 + q));
                }
            }
        }
    }
}

// ---- kernel 2: sort + walk (+ exact fallback) ----
__global__ void __launch_bounds__(NT) walk_kernel(
    const float* __restrict__ boxes,    // [B, N, 4]
    const float* __restrict__ scores,   // [B, C, N]
    float* __restrict__ out)            // [B*C*50, 3]
{
    __shared__ unsigned           hist[NBUCKET];    // fallback only
    __shared__ unsigned long long keys[CAP];
    __shared__ float cx1[CAP], cy1[CAP], cx2[CAP], cy2[CAP], car[CAP];
    __shared__ float ax1[64], ay1[64], ax2[64], ay2[64], aar[64];
    __shared__ int   sh_cnt, sh_lo, sh_acc;

    const int lane = blockIdx.x;
    const int b    = lane / NMS_C;
    const int c    = lane - b * NMS_C;
    const int tid  = threadIdx.x;

    const float* sc = scores + (size_t)lane * NMS_N;
    const float* bx = boxes + (size_t)b * NMS_N * 4;
    float* orow     = out + (size_t)lane * (NMS_MAXOUT * 3);

    const int total  = g_cnt[lane];
    const int cnt    = (total < CAP) ? total : CAP;
    const bool fastOK = (total <= CAP);

    int acc = 0;
    if (fastOK) {
        keys[tid] = (tid < cnt) ? g_keys[lane * CAP + tid] : 0ULL;
        __syncthreads();
        sort256(keys, tid);

        if (tid < cnt) {
            unsigned idx = ~(unsigned)keys[tid];
            size_t o = (size_t)idx * 4;
            float x1 = bx[o + 0], y1 = bx[o + 1];
            float x2 = bx[o + 2], y2 = bx[o + 3];
            cx1[tid] = x1; cy1[tid] = y1; cx2[tid] = x2; cy2[tid] = y2;
            car[tid] = __fmul_rn(x2 - x1, y2 - y1);
        }
        __syncthreads();

        if (tid < 32) {
            const int l = tid;
            int a = 0;
            for (int j2 = 0; j2 < cnt && a < NMS_MAXOUT; j2++) {
                float qx1 = cx1[j2], qy1 = cy1[j2];
                float qx2 = cx2[j2], qy2 = cy2[j2], qa = car[j2];
                bool rej = false;
                if (l < a)
                    rej = iou_reject(ax1[l], ay1[l], ax2[l], ay2[l], aar[l],
                                     qx1, qy1, qx2, qy2, qa);
                if (l + 32 < a)
                    rej |= iou_reject(ax1[l+32], ay1[l+32], ax2[l+32],
                                      ay2[l+32], aar[l+32],
                                      qx1, qy1, qx2, qy2, qa);
                if (__ballot_sync(0xffffffffu, rej) == 0u) {
                    if (l == 0) {
                        unsigned idx = ~(unsigned)keys[j2];
                        orow[a * 3 + 0] = (float)b;
                        orow[a * 3 + 1] = (float)c;
                        orow[a * 3 + 2] = (float)idx;
                        ax1[a] = qx1; ay1[a] = qy1;
                        ax2[a] = qx2; ay2[a] = qy2; aar[a] = qa;
                    }
                    __syncwarp();
                    a++;
                }
            }
            if (l == 0) sh_acc = a;
        }
        __syncthreads();
        acc = sh_acc;
    }

    // ---- exact fallback (block-uniform; statistically never taken) ----
    if (acc < NMS_MAXOUT) {
        for (int i = tid; i < NBUCKET; i += NT) hist[i] = 0;
        __syncthreads();
        for (int i = tid; i < NMS_N; i += NT) {
            float v = sc[i];
            if (v > SCORE_THR)
                atomicAdd(&hist[score_bucket(__float_as_uint(v))], 1u);
        }
        __syncthreads();

        int hi = fastOK ? T0_BUCKET : NBUCKET;
        while (acc < NMS_MAXOUT && hi > 0) {
            if (tid == 0) {
                unsigned cum = 0;
                int lo = hi;
                while (lo > 0) {
                    unsigned n2 = hist[lo - 1];
                    if (cum + n2 > CAP && cum > 0) break;
                    cum += n2;
                    lo--;
                    if (cum >= TARGET) break;
                }
                sh_lo  = lo;
                sh_cnt = 0;
            }
            __syncthreads();
            const int lo = sh_lo;

            for (int i = tid; i < NMS_N; i += NT) {
                float v = sc[i];
                if (v > SCORE_THR) {
                    unsigned bits = __float_as_uint(v);
                    int bkt = (int)score_bucket(bits);
                    if (bkt >= lo && bkt < hi) {
                        int pos = atomicAdd(&sh_cnt, 1);
                        if (pos < CAP)
                            keys[pos] = ((unsigned long long)bits << 32)
                                      | (unsigned)(~(unsigned)i);
                    }
                }
            }
            __syncthreads();
            const int n = (sh_cnt < CAP) ? sh_cnt : CAP;
            if (tid >= n) keys[tid] = 0ULL;
            __syncthreads();
            sort256(keys, tid);

            if (tid < n) {
                unsigned idx = ~(unsigned)keys[tid];
                size_t o = (size_t)idx * 4;
                float x1 = bx[o + 0], y1 = bx[o + 1];
                float x2 = bx[o + 2], y2 = bx[o + 3];
                cx1[tid] = x1; cy1[tid] = y1; cx2[tid] = x2; cy2[tid] = y2;
                car[tid] = __fmul_rn(x2 - x1, y2 - y1);
            }
            __syncthreads();

            if (tid < 32) {
                const int l = tid;
                int a = acc;
                for (int j2 = 0; j2 < n && a < NMS_MAXOUT; j2++) {
                    float qx1 = cx1[j2], qy1 = cy1[j2];
                    float qx2 = cx2[j2], qy2 = cy2[j2], qa = car[j2];
                    bool rej = false;
                    if (l < a)
                        rej = iou_reject(ax1[l], ay1[l], ax2[l], ay2[l], aar[l],
                                         qx1, qy1, qx2, qy2, qa);
                    if (l + 32 < a)
                        rej |= iou_reject(ax1[l+32], ay1[l+32], ax2[l+32],
                                          ay2[l+32], aar[l+32],
                                          qx1, qy1, qx2, qy2, qa);
                    if (__ballot_sync(0xffffffffu, rej) == 0u) {
                        if (l == 0) {
                            unsigned idx = ~(unsigned)keys[j2];
                            orow[a * 3 + 0] = (float)b;
                            orow[a * 3 + 1] = (float)c;
                            orow[a * 3 + 2] = (float)idx;
                            ax1[a] = qx1; ay1[a] = qy1;
                            ax2[a] = qx2; ay2[a] = qy2; aar[a] = qa;
                        }
                        __syncwarp();
                        a++;
                    }
                }
                if (l == 0) sh_acc = a;
            }
            __syncthreads();
            acc = sh_acc;
            hi  = lo;
        }
    }

    for (int j = acc * 3 + tid; j < NMS_MAXOUT * 3; j += NT)
        orow[j] = -1.0f;
}

extern "C" void kernel_launch(void* const* d_in, const int* in_sizes, int n_in,
                              void* d_out, int out_size)
{
    const float* boxes  = nullptr;   // 524288 elems
    const float* scores = nullptr;   // 10485760 elems
    for (int i = 0; i < n_in; i++) {
        int sz = in_sizes[i];
        if (sz == NMS_B * NMS_N * 4 || sz == NMS_B * NMS_N * 4 * 4)
            boxes = (const float*)d_in[i];
        else if (sz == NMS_B * NMS_C * NMS_N || sz == NMS_B * NMS_C * NMS_N * 4)
            scores = (const float*)d_in[i];
    }
    if (boxes  == nullptr) boxes  = (const float*)d_in[0];
    if (scores == nullptr) scores = (const float*)d_in[1];

    zero_kernel<<<(NMS_LANES + 255) / 256, 256>>>();
    gather_kernel<<<dim3(NMS_LANES, SPLIT), NT>>>(scores);
    walk_kernel<<<NMS_LANES, NT>>>(boxes, scores, (float*)d_out);
}

// round 14
// speedup vs baseline: 1.8153x; 1.8153x over previous
#include <cuda_runtime.h>

// OnnxNonMaxSuppression: B=8, C=80, N=16384, max_out=50. Output float32.
//
// Round-14: back to the single-kernel R12 shape (R13 phase-split paid a
// ~3.5us/launch floor and lost cross-phase overlap). Changes vs R12:
//  - rank sort (count-of-greater over distinct keys, broadcast LDS,
//    2 barriers) replaces the 36-barrier bitonic sort.
//  - candidate box loads issued BEFORE the rank loop; box+key scattered
//    directly to sorted position (prefetch overlapped with ranking).
//  - __launch_bounds__(256, 5) -> 5 blocks/SM, one wave.
// Exactness unchanged: sorted-walk == greedy NMS, reference IoU rounding,
// histogram-chunk fallback for overflow/shortfall.

#define NMS_B      8
#define NMS_C      80
#define NMS_N      16384
#define NMS_MAXOUT 50
#define NT         256
#define NBUCKET    1024
#define CAP        256
#define TARGET     128
#define IOU_THR    0.5f
#define SCORE_THR  0.5f
#define BITS_BASE  0x3F000001u                     // smallest float bits > 0.5f
#define T0_BUCKET  999
#define T0_BITS    (BITS_BASE + ((unsigned)T0_BUCKET << 13))

__device__ __forceinline__ unsigned score_bucket(unsigned bits) {
    unsigned bkt = (bits - BITS_BASE) >> 13;
    return bkt > (NBUCKET - 1) ? (NBUCKET - 1) : bkt;
}

// Reference-exact IoU rejection test (no-FMA, operand order preserved).
__device__ __forceinline__ bool iou_reject(
    float px1, float py1, float px2, float py2, float pa,
    float qx1, float qy1, float qx2, float qy2, float qa)
{
    float x1 = fmaxf(px1, qx1);
    float y1 = fmaxf(py1, qy1);
    float x2 = fminf(px2, qx2);
    float y2 = fminf(py2, qy2);
    float w  = fmaxf(x2 - x1, 0.0f);
    float h  = fmaxf(y2 - y1, 0.0f);
    float inter = __fmul_rn(w, h);
    float uni   = __fsub_rn(__fadd_rn(pa, qa), inter);
    float iou   = inter / fmaxf(uni, 1e-9f);
    return iou > IOU_THR;
}

__global__ void __launch_bounds__(NT, 5) nms_kernel(
    const float* __restrict__ boxes,    // [B, N, 4]
    const float* __restrict__ scores,   // [B, C, N]
    float* __restrict__ out)            // [B*C*50, 3] float32
{
    __shared__ unsigned           hist[NBUCKET];   // fallback only
    __shared__ unsigned long long keys[CAP];
    __shared__ float cx1[CAP], cy1[CAP], cx2[CAP], cy2[CAP], car[CAP];
    __shared__ float ax1[64], ay1[64], ax2[64], ay2[64], aar[64];
    __shared__ int   sh_cnt, sh_lo, sh_acc;

    const int lane = blockIdx.x;        // b*C + c
    const int b    = lane / NMS_C;
    const int c    = lane - b * NMS_C;
    const int tid  = threadIdx.x;

    const float*  sc  = scores + (size_t)lane * NMS_N;
    const float4* sc4 = reinterpret_cast<const float4*>(sc);
    const float*  bx  = boxes + (size_t)b * NMS_N * 4;
    float* orow       = out + (size_t)lane * (NMS_MAXOUT * 3);

    if (tid == 0) sh_cnt = 0;
    __syncthreads();

    // ---- streaming pass: collect top-chunk keys (unsorted) ----
    const float t0f = __uint_as_float(T0_BITS);    // positive-float bit order
    #pragma unroll 8
    for (int k = 0; k < NMS_N / (4 * NT); k++) {
        int    i4 = k * NT + tid;
        float4 v4 = sc4[i4];
        float vs[4] = {v4.x, v4.y, v4.z, v4.w};
        #pragma unroll
        for (int q = 0; q < 4; q++) {
            if (vs[q] >= t0f) {                    // == bits >= T0_BITS
                int pos = atomicAdd(&sh_cnt, 1);
                if (pos < CAP) {
                    unsigned bits = __float_as_uint(vs[q]);
                    keys[pos] = ((unsigned long long)bits << 32)
                              | (unsigned)(~(unsigned)(i4 * 4 + q));
                }
            }
        }
    }
    __syncthreads();

    int acc = 0;
    const int cnt     = sh_cnt;
    const bool fastOK = (cnt <= CAP);

    if (fastOK) {
        // ---- rank sort fused with box prefetch ----
        unsigned long long my = 0ULL;
        float x1 = 0, y1 = 0, x2 = 0, y2 = 0;
        if (tid < cnt) {
            my = keys[tid];
            unsigned idx = ~(unsigned)my;
            const float* p = bx + (size_t)idx * 4;
            x1 = p[0]; y1 = p[1]; x2 = p[2]; y2 = p[3];   // overlaps ranking
        }
        int rank = 0;
        if (tid < cnt) {
            #pragma unroll 4
            for (int j = 0; j < cnt; j++)
                rank += (keys[j] > my);            // distinct keys -> permutation
        }
        __syncthreads();
        if (tid < cnt) {
            keys[rank] = my;
            cx1[rank] = x1; cy1[rank] = y1; cx2[rank] = x2; cy2[rank] = y2;
            car[rank] = __fmul_rn(x2 - x1, y2 - y1);
        }
        __syncthreads();

        // ---- warp-0 ballot walk == greedy NMS ----
        if (tid < 32) {
            const int l = tid;
            int a = 0;
            for (int j2 = 0; j2 < cnt && a < NMS_MAXOUT; j2++) {
                float qx1 = cx1[j2], qy1 = cy1[j2];
                float qx2 = cx2[j2], qy2 = cy2[j2], qa = car[j2];
                bool rej = false;
                if (l < a)
                    rej = iou_reject(ax1[l], ay1[l], ax2[l], ay2[l], aar[l],
                                     qx1, qy1, qx2, qy2, qa);
                if (l + 32 < a)
                    rej |= iou_reject(ax1[l+32], ay1[l+32], ax2[l+32],
                                      ay2[l+32], aar[l+32],
                                      qx1, qy1, qx2, qy2, qa);
                if (__ballot_sync(0xffffffffu, rej) == 0u) {
                    if (l == 0) {
                        unsigned idx = ~(unsigned)keys[j2];
                        orow[a * 3 + 0] = (float)b;
                        orow[a * 3 + 1] = (float)c;
                        orow[a * 3 + 2] = (float)idx;
                        ax1[a] = qx1; ay1[a] = qy1;
                        ax2[a] = qx2; ay2[a] = qy2; aar[a] = qa;
                    }
                    __syncwarp();
                    a++;
                }
            }
            if (l == 0) sh_acc = a;
        }
        __syncthreads();
        acc = sh_acc;
    }

    // ---- exact fallback (block-uniform; statistically never taken) ----
    if (acc < NMS_MAXOUT) {
        for (int i = tid; i < NBUCKET; i += NT) hist[i] = 0;
        __syncthreads();
        for (int i = tid; i < NMS_N; i += NT) {
            float v = sc[i];
            if (v > SCORE_THR)
                atomicAdd(&hist[score_bucket(__float_as_uint(v))], 1u);
        }
        __syncthreads();

        int hi = fastOK ? T0_BUCKET : NBUCKET;
        while (acc < NMS_MAXOUT && hi > 0) {
            if (tid == 0) {
                unsigned cum = 0;
                int lo = hi;
                while (lo > 0) {
                    unsigned n2 = hist[lo - 1];
                    if (cum + n2 > CAP && cum > 0) break;
                    cum += n2;
                    lo--;
                    if (cum >= TARGET) break;
                }
                sh_lo  = lo;
                sh_cnt = 0;
            }
            __syncthreads();
            const int lo = sh_lo;

            for (int i = tid; i < NMS_N; i += NT) {
                float v = sc[i];
                if (v > SCORE_THR) {
                    unsigned bits = __float_as_uint(v);
                    int bkt = (int)score_bucket(bits);
                    if (bkt >= lo && bkt < hi) {
                        int pos = atomicAdd(&sh_cnt, 1);
                        if (pos < CAP)
                            keys[pos] = ((unsigned long long)bits << 32)
                                      | (unsigned)(~(unsigned)i);
                    }
                }
            }
            __syncthreads();
            const int n = (sh_cnt < CAP) ? sh_cnt : CAP;

            // rank sort + prefetch (same as fast path)
            unsigned long long my = 0ULL;
            float x1 = 0, y1 = 0, x2 = 0, y2 = 0;
            if (tid < n) {
                my = keys[tid];
                unsigned idx = ~(unsigned)my;
                const float* p = bx + (size_t)idx * 4;
                x1 = p[0]; y1 = p[1]; x2 = p[2]; y2 = p[3];
            }
            int rank = 0;
            if (tid < n) {
                #pragma unroll 4
                for (int j = 0; j < n; j++)
                    rank += (keys[j] > my);
            }
            __syncthreads();
            if (tid < n) {
                keys[rank] = my;
                cx1[rank] = x1; cy1[rank] = y1; cx2[rank] = x2; cy2[rank] = y2;
                car[rank] = __fmul_rn(x2 - x1, y2 - y1);
            }
            __syncthreads();

            if (tid < 32) {
                const int l = tid;
                int a = acc;
                for (int j2 = 0; j2 < n && a < NMS_MAXOUT; j2++) {
                    float qx1 = cx1[j2], qy1 = cy1[j2];
                    float qx2 = cx2[j2], qy2 = cy2[j2], qa = car[j2];
                    bool rej = false;
                    if (l < a)
                        rej = iou_reject(ax1[l], ay1[l], ax2[l], ay2[l], aar[l],
                                         qx1, qy1, qx2, qy2, qa);
                    if (l + 32 < a)
                        rej |= iou_reject(ax1[l+32], ay1[l+32], ax2[l+32],
                                          ay2[l+32], aar[l+32],
                                          qx1, qy1, qx2, qy2, qa);
                    if (__ballot_sync(0xffffffffu, rej) == 0u) {
                        if (l == 0) {
                            unsigned idx = ~(unsigned)keys[j2];
                            orow[a * 3 + 0] = (float)b;
                            orow[a * 3 + 1] = (float)c;
                            orow[a * 3 + 2] = (float)idx;
                            ax1[a] = qx1; ay1[a] = qy1;
                            ax2[a] = qx2; ay2[a] = qy2; aar[a] = qa;
                        }
                        __syncwarp();
                        a++;
                    }
                }
                if (l == 0) sh_acc = a;
            }
            __syncthreads();
            acc = sh_acc;
            hi  = lo;
        }
    }

    // ---- pad remaining rows with -1 ----
    for (int j = acc * 3 + tid; j < NMS_MAXOUT * 3; j += NT)
        orow[j] = -1.0f;
}

extern "C" void kernel_launch(void* const* d_in, const int* in_sizes, int n_in,
                              void* d_out, int out_size)
{
    const float* boxes  = nullptr;   // 524288 elems
    const float* scores = nullptr;   // 10485760 elems
    for (int i = 0; i < n_in; i++) {
        int sz = in_sizes[i];
        if (sz == NMS_B * NMS_N * 4 || sz == NMS_B * NMS_N * 4 * 4)
            boxes = (const float*)d_in[i];
        else if (sz == NMS_B * NMS_C * NMS_N || sz == NMS_B * NMS_C * NMS_N * 4)
            scores = (const float*)d_in[i];
    }
    if (boxes  == nullptr) boxes  = (const float*)d_in[0];
    if (scores == nullptr) scores = (const float*)d_in[1];

    nms_kernel<<<NMS_B * NMS_C, NT>>>(boxes, scores, (float*)d_out);
}

// round 15
// speedup vs baseline: 2.0355x; 1.1213x over previous
#include <cuda_runtime.h>

// OnnxNonMaxSuppression: B=8, C=80, N=16384, max_out=50. Output float32.
//
// Round-15 vs R14 (48.5us):
//  - __launch_bounds__(256, 4): 64-reg budget so ptxas can front-batch
//    ~8-10 of the 16 float4 score loads (R14's 48-reg cap limited MLP).
//  - fmax-tree fast-reject per float4 (3 ops + 1 branch) replaces 4
//    independent compare+branch chains in the 99% no-candidate case.
//  - collection threshold raised to top-13 buckets (E[cnt]~104): rank
//    loop halves. Exact histogram fallback unchanged (covers shortfall).
// Exactness unchanged: sorted-walk == greedy NMS, reference IoU rounding.

#define NMS_B      8
#define NMS_C      80
#define NMS_N      16384
#define NMS_MAXOUT 50
#define NT         256
#define NBUCKET    1024
#define CAP        256
#define TARGET     128
#define IOU_THR    0.5f
#define SCORE_THR  0.5f
#define BITS_BASE  0x3F000001u                     // smallest float bits > 0.5f
#define T0_BUCKET  1011                            // top 13 buckets, E~104
#define T0_BITS    (BITS_BASE + ((unsigned)T0_BUCKET << 13))

__device__ __forceinline__ unsigned score_bucket(unsigned bits) {
    unsigned bkt = (bits - BITS_BASE) >> 13;
    return bkt > (NBUCKET - 1) ? (NBUCKET - 1) : bkt;
}

// Reference-exact IoU rejection test (no-FMA, operand order preserved).
__device__ __forceinline__ bool iou_reject(
    float px1, float py1, float px2, float py2, float pa,
    float qx1, float qy1, float qx2, float qy2, float qa)
{
    float x1 = fmaxf(px1, qx1);
    float y1 = fmaxf(py1, qy1);
    float x2 = fminf(px2, qx2);
    float y2 = fminf(py2, qy2);
    float w  = fmaxf(x2 - x1, 0.0f);
    float h  = fmaxf(y2 - y1, 0.0f);
    float inter = __fmul_rn(w, h);
    float uni   = __fsub_rn(__fadd_rn(pa, qa), inter);
    float iou   = inter / fmaxf(uni, 1e-9f);
    return iou > IOU_THR;
}

__global__ void __launch_bounds__(NT, 4) nms_kernel(
    const float* __restrict__ boxes,    // [B, N, 4]
    const float* __restrict__ scores,   // [B, C, N]
    float* __restrict__ out)            // [B*C*50, 3] float32
{
    __shared__ unsigned           hist[NBUCKET];   // fallback only
    __shared__ unsigned long long keys[CAP];
    __shared__ float cx1[CAP], cy1[CAP], cx2[CAP], cy2[CAP], car[CAP];
    __shared__ float ax1[64], ay1[64], ax2[64], ay2[64], aar[64];
    __shared__ int   sh_cnt, sh_lo, sh_acc;

    const int lane = blockIdx.x;        // b*C + c
    const int b    = lane / NMS_C;
    const int c    = lane - b * NMS_C;
    const int tid  = threadIdx.x;

    const float*  sc  = scores + (size_t)lane * NMS_N;
    const float4* sc4 = reinterpret_cast<const float4*>(sc);
    const float*  bx  = boxes + (size_t)b * NMS_N * 4;
    float* orow       = out + (size_t)lane * (NMS_MAXOUT * 3);

    if (tid == 0) sh_cnt = 0;
    __syncthreads();

    // ---- streaming pass: collect top-chunk keys (unsorted) ----
    const float t0f = __uint_as_float(T0_BITS);    // positive-float bit order
    #pragma unroll
    for (int k = 0; k < NMS_N / (4 * NT); k++) {   // 16 float4 per thread
        int    i4 = k * NT + tid;
        float4 v4 = sc4[i4];
        // fast reject: does ANY of the 4 reach the threshold?
        float m = fmaxf(fmaxf(v4.x, v4.y), fmaxf(v4.z, v4.w));
        if (m >= t0f) {                            // rare (~2.5% of float4s)
            float vs[4] = {v4.x, v4.y, v4.z, v4.w};
            #pragma unroll
            for (int q = 0; q < 4; q++) {
                if (vs[q] >= t0f) {                // == bits >= T0_BITS
                    int pos = atomicAdd(&sh_cnt, 1);
                    if (pos < CAP) {
                        unsigned bits = __float_as_uint(vs[q]);
                        keys[pos] = ((unsigned long long)bits << 32)
                                  | (unsigned)(~(unsigned)(i4 * 4 + q));
                    }
                }
            }
        }
    }
    __syncthreads();

    int acc = 0;
    const int cnt     = sh_cnt;
    const bool fastOK = (cnt <= CAP);

    if (fastOK) {
        // ---- rank sort fused with box prefetch ----
        unsigned long long my = 0ULL;
        float x1 = 0, y1 = 0, x2 = 0, y2 = 0;
        if (tid < cnt) {
            my = keys[tid];
            unsigned idx = ~(unsigned)my;
            const float* p = bx + (size_t)idx * 4;
            x1 = p[0]; y1 = p[1]; x2 = p[2]; y2 = p[3];   // overlaps ranking
        }
        int rank = 0;
        if (tid < cnt) {
            #pragma unroll 4
            for (int j = 0; j < cnt; j++)
                rank += (keys[j] > my);            // distinct keys -> permutation
        }
        __syncthreads();
        if (tid < cnt) {
            keys[rank] = my;
            cx1[rank] = x1; cy1[rank] = y1; cx2[rank] = x2; cy2[rank] = y2;
            car[rank] = __fmul_rn(x2 - x1, y2 - y1);
        }
        __syncthreads();

        // ---- warp-0 ballot walk == greedy NMS ----
        if (tid < 32) {
            const int l = tid;
            int a = 0;
            for (int j2 = 0; j2 < cnt && a < NMS_MAXOUT; j2++) {
                float qx1 = cx1[j2], qy1 = cy1[j2];
                float qx2 = cx2[j2], qy2 = cy2[j2], qa = car[j2];
                bool rej = false;
                if (l < a)
                    rej = iou_reject(ax1[l], ay1[l], ax2[l], ay2[l], aar[l],
                                     qx1, qy1, qx2, qy2, qa);
                if (l + 32 < a)
                    rej |= iou_reject(ax1[l+32], ay1[l+32], ax2[l+32],
                                      ay2[l+32], aar[l+32],
                                      qx1, qy1, qx2, qy2, qa);
                if (__ballot_sync(0xffffffffu, rej) == 0u) {
                    if (l == 0) {
                        unsigned idx = ~(unsigned)keys[j2];
                        orow[a * 3 + 0] = (float)b;
                        orow[a * 3 + 1] = (float)c;
                        orow[a * 3 + 2] = (float)idx;
                        ax1[a] = qx1; ay1[a] = qy1;
                        ax2[a] = qx2; ay2[a] = qy2; aar[a] = qa;
                    }
                    __syncwarp();
                    a++;
                }
            }
            if (l == 0) sh_acc = a;
        }
        __syncthreads();
        acc = sh_acc;
    }

    // ---- exact fallback (block-uniform; statistically never taken) ----
    if (acc < NMS_MAXOUT) {
        for (int i = tid; i < NBUCKET; i += NT) hist[i] = 0;
        __syncthreads();
        for (int i = tid; i < NMS_N; i += NT) {
            float v = sc[i];
            if (v > SCORE_THR)
                atomicAdd(&hist[score_bucket(__float_as_uint(v))], 1u);
        }
        __syncthreads();

        int hi = fastOK ? T0_BUCKET : NBUCKET;
        while (acc < NMS_MAXOUT && hi > 0) {
            if (tid == 0) {
                unsigned cum = 0;
                int lo = hi;
                while (lo > 0) {
                    unsigned n2 = hist[lo - 1];
                    if (cum + n2 > CAP && cum > 0) break;
                    cum += n2;
                    lo--;
                    if (cum >= TARGET) break;
                }
                sh_lo  = lo;
                sh_cnt = 0;
            }
            __syncthreads();
            const int lo = sh_lo;

            for (int i = tid; i < NMS_N; i += NT) {
                float v = sc[i];
                if (v > SCORE_THR) {
                    unsigned bits = __float_as_uint(v);
                    int bkt = (int)score_bucket(bits);
                    if (bkt >= lo && bkt < hi) {
                        int pos = atomicAdd(&sh_cnt, 1);
                        if (pos < CAP)
                            keys[pos] = ((unsigned long long)bits << 32)
                                      | (unsigned)(~(unsigned)i);
                    }
                }
            }
            __syncthreads();
            const int n = (sh_cnt < CAP) ? sh_cnt : CAP;

            unsigned long long my = 0ULL;
            float x1 = 0, y1 = 0, x2 = 0, y2 = 0;
            if (tid < n) {
                my = keys[tid];
                unsigned idx = ~(unsigned)my;
                const float* p = bx + (size_t)idx * 4;
                x1 = p[0]; y1 = p[1]; x2 = p[2]; y2 = p[3];
            }
            int rank = 0;
            if (tid < n) {
                #pragma unroll 4
                for (int j = 0; j < n; j++)
                    rank += (keys[j] > my);
            }
            __syncthreads();
            if (tid < n) {
                keys[rank] = my;
                cx1[rank] = x1; cy1[rank] = y1; cx2[rank] = x2; cy2[rank] = y2;
                car[rank] = __fmul_rn(x2 - x1, y2 - y1);
            }
            __syncthreads();

            if (tid < 32) {
                const int l = tid;
                int a = acc;
                for (int j2 = 0; j2 < n && a < NMS_MAXOUT; j2++) {
                    float qx1 = cx1[j2], qy1 = cy1[j2];
                    float qx2 = cx2[j2], qy2 = cy2[j2], qa = car[j2];
                    bool rej = false;
                    if (l < a)
                        rej = iou_reject(ax1[l], ay1[l], ax2[l], ay2[l], aar[l],
                                         qx1, qy1, qx2, qy2, qa);
                    if (l + 32 < a)
                        rej |= iou_reject(ax1[l+32], ay1[l+32], ax2[l+32],
                                          ay2[l+32], aar[l+32],
                                          qx1, qy1, qx2, qy2, qa);
                    if (__ballot_sync(0xffffffffu, rej) == 0u) {
                        if (l == 0) {
                            unsigned idx = ~(unsigned)keys[j2];
                            orow[a * 3 + 0] = (float)b;
                            orow[a * 3 + 1] = (float)c;
                            orow[a * 3 + 2] = (float)idx;
                            ax1[a] = qx1; ay1[a] = qy1;
                            ax2[a] = qx2; ay2[a] = qy2; aar[a] = qa;
                        }
                        __syncwarp();
                        a++;
                    }
                }
                if (l == 0) sh_acc = a;
            }
            __syncthreads();
            acc = sh_acc;
            hi  = lo;
        }
    }

    // ---- pad remaining rows with -1 ----
    for (int j = acc * 3 + tid; j < NMS_MAXOUT * 3; j += NT)
        orow[j] = -1.0f;
}

extern "C" void kernel_launch(void* const* d_in, const int* in_sizes, int n_in,
                              void* d_out, int out_size)
{
    const float* boxes  = nullptr;   // 524288 elems
    const float* scores = nullptr;   // 10485760 elems
    for (int i = 0; i < n_in; i++) {
        int sz = in_sizes[i];
        if (sz == NMS_B * NMS_N * 4 || sz == NMS_B * NMS_N * 4 * 4)
            boxes = (const float*)d_in[i];
        else if (sz == NMS_B * NMS_C * NMS_N || sz == NMS_B * NMS_C * NMS_N * 4)
            scores = (const float*)d_in[i];
    }
    if (boxes  == nullptr) boxes  = (const float*)d_in[0];
    if (scores == nullptr) scores = (const float*)d_in[1];

    nms_kernel<<<NMS_B * NMS_C, NT>>>(boxes, scores, (float*)d_out);
}